// round 10
// baseline (speedup 1.0000x reference)
#include <cuda_runtime.h>
#include <math.h>

#define NROW 512
#define CZ   128
#define NPAIR (NROW * NROW) /* 262144 */

typedef unsigned int u32;

// ---------------- device scratch ----------------
__device__ float g_A[(size_t)CZ * NPAIR];   // a, [c][i*512 + kperm]
__device__ float g_B[(size_t)CZ * NPAIR];   // b, [c][j*512 + kperm]
__device__ float g_G[(size_t)NPAIR * CZ];   // gate, [pair][cz]  (natural)
__device__ float g_T[(size_t)CZ * NPAIR];   // t, [c][i*512+j]
__device__ float g_wt[6 * 128 * 128];       // weights, pair layout [n][128]
// img order: 0 w_ap, 1 w_ag, 2 w_bp, 3 w_bg, 4 w_g, 5 w_z

// ---------------- helpers ----------------
__device__ __forceinline__ float tf32r(float x) {
    float r;
    asm("cvt.rna.tf32.f32 %0, %1;" : "=f"(r) : "f"(x));
    return r;
}
__device__ __forceinline__ float wsum(float v) {
#pragma unroll
    for (int o = 16; o; o >>= 1) v += __shfl_xor_sync(0xffffffffu, v, o);
    return v;
}
__device__ __forceinline__ float sigm(float x) {
    return 1.0f / (1.0f + __expf(-x));
}
__device__ __forceinline__ void mma8(float* d, const u32* a, const u32* b) {
    asm volatile(
        "mma.sync.aligned.m16n8k8.row.col.f32.tf32.tf32.f32 "
        "{%0,%1,%2,%3}, {%4,%5,%6,%7}, {%8,%9}, {%0,%1,%2,%3};"
        : "+f"(d[0]), "+f"(d[1]), "+f"(d[2]), "+f"(d[3])
        : "r"(a[0]), "r"(a[1]), "r"(a[2]), "r"(a[3]), "r"(b[0]), "r"(b[1]));
}
__device__ __forceinline__ u32 smem_u32(const void* p) {
    u32 a;
    asm("{ .reg .u64 t; cvta.to.shared.u64 t, %1; cvt.u32.u64 %0, t; }" : "=r"(a) : "l"(p));
    return a;
}
__device__ __forceinline__ void cpa16(u32 dst, const void* src) {
    asm volatile("cp.async.cg.shared.global [%0], [%1], 16;" :: "r"(dst), "l"(src));
}
#define CP_COMMIT() asm volatile("cp.async.commit_group;" ::: "memory")
#define CP_WAIT(n)  asm volatile("cp.async.wait_group %0;" :: "n"(n) : "memory")

// ============================================================================
// prep: transpose + tf32-round weights into pair layout:
// g_wt[img][n*128 + (k>>3)*8 + (k&3)*2 + ((k&4)>>2)]
// ============================================================================
__global__ void prep_w(const float* __restrict__ wap, const float* __restrict__ wag,
                       const float* __restrict__ wbp, const float* __restrict__ wbg,
                       const float* __restrict__ wg,  const float* __restrict__ wz) {
    int img = blockIdx.y;
    int lin = blockIdx.x * 256 + threadIdx.x;
    int n = lin >> 7, k = lin & 127;
    const float* s;
    switch (img) {
        case 0: s = wap; break; case 1: s = wag; break;
        case 2: s = wbp; break; case 3: s = wbg; break;
        case 4: s = wg;  break; default: s = wz; break;
    }
    int pos = n * 128 + (k >> 3) * 8 + (k & 3) * 2 + ((k & 4) >> 2);
    g_wt[img * 16384 + pos] = tf32r(s[k * 128 + n]);
}

// ============================================================================
// load a 64-row weight chunk (rows nb..nb+63 of image img) into Wc
// ============================================================================
__device__ __forceinline__ void loadWc(float* __restrict__ Wc, int img, int nb, int tid) {
    const float4* src = (const float4*)(g_wt + img * 16384);
#pragma unroll
    for (int it = 0; it < 8; ++it) {
        int lin = it * 256 + tid;          // 0..2047
        int row = lin >> 5, q = lin & 31;
        ((float4*)Wc)[row * 34 + q] = src[(nb + row) * 32 + q];
    }
}

// GEMM: warp tile m16 x n32, K=128. As pair layout (stride 68 f2),
// Wc pair layout (64 rows, stride 68 f2). acc[4][4].
__device__ __forceinline__ void gemm32(const float2* __restrict__ As2,
                                       const float2* __restrict__ Wc2,
                                       int aoff, int boff0, float acc[4][4]) {
#pragma unroll
    for (int i = 0; i < 4; ++i)
#pragma unroll
        for (int q = 0; q < 4; ++q) acc[i][q] = 0.f;
#pragma unroll
    for (int ks = 0; ks < 16; ++ks) {
        float2 a0 = As2[aoff + ks * 4];
        float2 a1 = As2[aoff + ks * 4 + 544];   // +8 rows
        u32 aa[4] = { __float_as_uint(a0.x), __float_as_uint(a1.x),
                      __float_as_uint(a0.y), __float_as_uint(a1.y) };
#pragma unroll
        for (int nt = 0; nt < 4; ++nt) {
            float2 b = Wc2[boff0 + nt * 8 * 68 + ks * 4];
            u32 bb[2] = { __float_as_uint(b.x), __float_as_uint(b.y) };
            mma8(acc[nt], aa, bb);
        }
    }
}

// shared LN into As (pair layout); 8 warps x 8 rows = 64 pairs
__device__ __forceinline__ void ln_tile64(const float* __restrict__ z, size_t pair0,
                                          float* __restrict__ As,
                                          const float* __restrict__ lnw,
                                          const float* __restrict__ lnb,
                                          int wid, int lane) {
    float4 lw = ((const float4*)lnw)[lane];
    float4 lb = ((const float4*)lnb)[lane];
#pragma unroll 2
    for (int r = 0; r < 8; ++r) {
        int row = wid * 8 + r;
        float4 x = ((const float4*)(z + (pair0 + row) * (size_t)CZ))[lane];
        float m = wsum(x.x + x.y + x.z + x.w) * (1.0f / 128.0f);
        float dx = x.x - m, dy = x.y - m, dz = x.z - m, dw = x.w - m;
        float var = wsum(dx * dx + dy * dy + dz * dz + dw * dw) * (1.0f / 128.0f);
        float rs = rsqrtf(var + 1e-5f);
        float* dst = As + row * 136 + (lane >> 1) * 8 + (lane & 1);
        dst[0] = tf32r(dx * rs * lw.x + lb.x);
        dst[2] = tf32r(dy * rs * lw.y + lb.y);
        dst[4] = tf32r(dz * rs * lw.z + lb.z);
        dst[6] = tf32r(dw * rs * lw.w + lb.w);
    }
}

// ============================================================================
// proj_ab: 64-pair tiles, LN once, 8 GEMM passes -> g_A, g_B (k-permuted).
// smem = As(64x136) + Wc(64x136) = 69632B -> 3 CTAs/SM.
// ============================================================================
__global__ __launch_bounds__(256, 3) void proj_ab_kernel(
    const float* __restrict__ z,
    const float* __restrict__ lnw, const float* __restrict__ lnb,
    const float* __restrict__ b_ap, const float* __restrict__ b_ag,
    const float* __restrict__ b_bp, const float* __restrict__ b_bg)
{
    extern __shared__ float smf[];
    float* As = smf;                 // 64 x 136
    float* Wc = smf + 64 * 136;      // 64 x 136
    const int tid = threadIdx.x;
    const int wid = tid >> 5, lane = tid & 31;
    const int g = lane >> 2, t = lane & 3;
    const int m0 = (wid & 3) * 16, n0 = (wid >> 2) * 32;
    const size_t pair0 = (size_t)blockIdx.x * 64;

    ln_tile64(z, pair0, As, lnw, lnb, wid, lane);

    const float2* As2 = (const float2*)As;
    const float2* Wc2 = (const float2*)Wc;
    const int aoff = (m0 + g) * 68 + t;
    const int boff0 = (n0 + g) * 68 + t;
    const int rp = m0 + (g & 3) * 2 + (g >> 2);     // permuted row

    float accg[4][4], accp[4][4];

#pragma unroll 1
    for (int sel = 0; sel < 2; ++sel) {
        const int imgP = sel * 2, imgG = sel * 2 + 1;
        const float* bp = sel ? b_bp : b_ap;
        const float* bg = sel ? b_bg : b_ag;
        float* __restrict__ dst = sel ? g_B : g_A;
#pragma unroll 1
        for (int cb = 0; cb < 128; cb += 64) {
            __syncthreads();
            loadWc(Wc, imgG, cb, tid);
            __syncthreads();
            gemm32(As2, Wc2, aoff, boff0, accg);
            __syncthreads();
            loadWc(Wc, imgP, cb, tid);
            __syncthreads();
            gemm32(As2, Wc2, aoff, boff0, accp);
#pragma unroll
            for (int nt = 0; nt < 4; ++nt) {
                int c = cb + n0 + nt * 8 + 2 * t;
                float2 bpv = *(const float2*)(bp + c);
                float2 bgv = *(const float2*)(bg + c);
                float* d0 = dst + (size_t)c * NPAIR + pair0;
                float* d1 = dst + (size_t)(c + 1) * NPAIR + pair0;
                d0[rp]     = tf32r(sigm(accg[nt][0] + bgv.x) * (accp[nt][0] + bpv.x));
                d1[rp]     = tf32r(sigm(accg[nt][1] + bgv.y) * (accp[nt][1] + bpv.y));
                d0[rp + 8] = tf32r(sigm(accg[nt][2] + bgv.x) * (accp[nt][2] + bpv.x));
                d1[rp + 8] = tf32r(sigm(accg[nt][3] + bgv.y) * (accp[nt][3] + bpv.y));
            }
        }
    }
}

// ============================================================================
// proj_g: 64-pair tiles, LN + 2 GEMM passes -> g_G (natural [pair][cz]).
// Runs CONCURRENTLY with tri (it does not touch g_A/g_B/g_T).
// ============================================================================
__global__ __launch_bounds__(256, 3) void proj_g_kernel(
    const float* __restrict__ z,
    const float* __restrict__ lnw, const float* __restrict__ lnb,
    const float* __restrict__ b_g)
{
    extern __shared__ float smf[];
    float* As = smf;                 // 64 x 136
    float* Wc = smf + 64 * 136;      // 64 x 136
    const int tid = threadIdx.x;
    const int wid = tid >> 5, lane = tid & 31;
    const int g = lane >> 2, t = lane & 3;
    const int m0 = (wid & 3) * 16, n0 = (wid >> 2) * 32;
    const size_t pair0 = (size_t)blockIdx.x * 64;

    ln_tile64(z, pair0, As, lnw, lnb, wid, lane);

    const float2* As2 = (const float2*)As;
    const float2* Wc2 = (const float2*)Wc;
    const int aoff = (m0 + g) * 68 + t;
    const int boff0 = (n0 + g) * 68 + t;
    const int r = m0 + g;

    float accg[4][4];

#pragma unroll 1
    for (int cb = 0; cb < 128; cb += 64) {
        __syncthreads();
        loadWc(Wc, 4, cb, tid);
        __syncthreads();
        gemm32(As2, Wc2, aoff, boff0, accg);
#pragma unroll
        for (int nt = 0; nt < 4; ++nt) {
            int c = cb + n0 + nt * 8 + 2 * t;
            float2 bgv = *(const float2*)(b_g + c);
            *(float2*)(g_G + (pair0 + r) * (size_t)CZ + c) =
                make_float2(sigm(accg[nt][0] + bgv.x), sigm(accg[nt][1] + bgv.y));
            *(float2*)(g_G + (pair0 + r + 8) * (size_t)CZ + c) =
                make_float2(sigm(accg[nt][2] + bgv.x), sigm(accg[nt][3] + bgv.y));
        }
    }
}

// ============================================================================
// tri: t[c][i][j] = sum_k a[c][i][k]*b[c][j][k]; 128x128 tile, K chunks of 32,
// cp.async DOUBLE-buffered. smem 80KB -> 2 CTAs/SM (reg-capped anyway).
// ============================================================================
__global__ __launch_bounds__(256, 2) void tri_kernel()
{
    extern __shared__ float smf[];   // [buf][A 5120 | B 5120] floats
    const int tid = threadIdx.x;
    const int wid = tid >> 5, lane = tid & 31;
    const int g = lane >> 2, t = lane & 3;
    const int m0 = (wid & 3) * 32, n0 = (wid >> 2) * 64;
    const int c  = blockIdx.z;
    const int i0 = blockIdx.y * 128;
    const int j0 = blockIdx.x * 128;
    const float* __restrict__ asrc = g_A + (size_t)c * NPAIR + (size_t)i0 * NROW;
    const float* __restrict__ bsrc = g_B + (size_t)c * NPAIR + (size_t)j0 * NROW;
    const u32 smb = smem_u32(smf);

    auto issue = [&](int s) {
        const int k0 = s * 32;
        const u32 base = smb + (u32)(s & 1) * 10240u * 4u;
#pragma unroll
        for (int it = 0; it < 4; ++it) {
            int lin = it * 256 + tid;      // 0..1023
            int row = lin >> 3, j = lin & 7;
            u32 doff = (u32)(row * 40 + j * 4) * 4u;
            cpa16(base + doff, asrc + (size_t)row * NROW + k0 + j * 4);
            cpa16(base + 5120u * 4u + doff, bsrc + (size_t)row * NROW + k0 + j * 4);
        }
    };

    float acc[2][8][4];
#pragma unroll
    for (int i = 0; i < 2; ++i)
#pragma unroll
        for (int j = 0; j < 8; ++j)
#pragma unroll
            for (int q = 0; q < 4; ++q) acc[i][j][q] = 0.f;

    const int aoff = (m0 + g) * 20 + t;
    int boff[8];
#pragma unroll
    for (int nt = 0; nt < 8; ++nt) boff[nt] = (n0 + nt * 8 + g) * 20 + t;

    issue(0); CP_COMMIT();

#pragma unroll 1
    for (int kc = 0; kc < 16; ++kc) {
        if (kc < 15) { issue(kc + 1); CP_COMMIT(); CP_WAIT(1); }
        else         { CP_WAIT(0); }
        __syncthreads();

        const float2* A2 = (const float2*)(smf + (kc & 1) * 10240);
        const float2* B2 = (const float2*)(smf + (kc & 1) * 10240 + 5120);
#pragma unroll
        for (int ks = 0; ks < 4; ++ks) {
            float2 a00 = A2[aoff + ks * 4];
            float2 a01 = A2[aoff + ks * 4 + 160];
            float2 a10 = A2[aoff + ks * 4 + 320];
            float2 a11 = A2[aoff + ks * 4 + 480];
            u32 aa0[4] = { __float_as_uint(a00.x), __float_as_uint(a01.x),
                           __float_as_uint(a00.y), __float_as_uint(a01.y) };
            u32 aa1[4] = { __float_as_uint(a10.x), __float_as_uint(a11.x),
                           __float_as_uint(a10.y), __float_as_uint(a11.y) };
#pragma unroll
            for (int nt = 0; nt < 8; ++nt) {
                float2 b = B2[boff[nt] + ks * 4];
                u32 bb[2] = { __float_as_uint(b.x), __float_as_uint(b.y) };
                mma8(acc[0][nt], aa0, bb);
                mma8(acc[1][nt], aa1, bb);
            }
        }
        __syncthreads();
    }

    float* __restrict__ tdst = g_T + (size_t)c * NPAIR;
#pragma unroll
    for (int mt = 0; mt < 2; ++mt) {
        int r = i0 + m0 + mt * 16 + g;
#pragma unroll
        for (int nt = 0; nt < 8; ++nt) {
            int cl = j0 + n0 + nt * 8 + 2 * t;
            *(float2*)(tdst + (size_t)r * NROW + cl) =
                make_float2(acc[mt][nt][0], acc[mt][nt][1]);
            *(float2*)(tdst + (size_t)(r + 8) * NROW + cl) =
                make_float2(acc[mt][nt][2], acc[mt][nt][3]);
        }
    }
}

// ============================================================================
// final: out[pair][cz] = g * (LN_c(t) @ Wz + bz). 64-pair tiles, grid 4096.
// t gathered via cp.async; gate in natural layout (coalesced with out).
// smem = As(128x72) + Wc(64x136) + stats = 74240B -> 3 CTAs/SM.
// ============================================================================
__global__ __launch_bounds__(256, 3) void final_kernel(
    const float* __restrict__ lnw, const float* __restrict__ lnb,
    const float* __restrict__ bz, float* __restrict__ out)
{
    extern __shared__ float smf[];
    float* As = smf;                 // [128 c][72 pair] k-major
    float* Wc = As + 128 * 72;       // 64 x 136
    float* PS = Wc + 64 * 136;       // 256
    float* PQ = PS + 256;            // 256
    float* MS = PQ + 256;            // 64
    float* RS = MS + 64;             // 64
    const int tid = threadIdx.x;
    const int wid = tid >> 5, lane = tid & 31;
    const int g = lane >> 2, t = lane & 3;
    const int m0 = (wid & 3) * 16, n0 = (wid >> 2) * 32;
    const int p = tid & 63, ch = tid >> 6;
    const size_t pair0 = (size_t)blockIdx.x * 64;
    const u32 smb = smem_u32(smf);

    // ---- async gather of t: 2048 x 16B ----
#pragma unroll
    for (int it = 0; it < 8; ++it) {
        int lin = it * 256 + tid;        // 0..2047
        int c = lin >> 4, p4 = lin & 15;
        cpa16(smb + (u32)(c * 72 + p4 * 4) * 4u,
              g_T + (size_t)c * NPAIR + pair0 + p4 * 4);
    }
    CP_COMMIT();
    CP_WAIT(0);
    __syncthreads();

    // ---- stats from smem ----
    {
        float s = 0.f, qq = 0.f;
#pragma unroll 4
        for (int cc = 0; cc < 32; ++cc) {
            int c = ch * 32 + cc;
            float v = As[c * 72 + p];
            s += v; qq += v * v;
        }
        PS[tid] = s; PQ[tid] = qq;
    }
    __syncthreads();
    if (tid < 64) {
        float ss = PS[tid] + PS[tid + 64] + PS[tid + 128] + PS[tid + 192];
        float sq = PQ[tid] + PQ[tid + 64] + PQ[tid + 128] + PQ[tid + 192];
        float m = ss * (1.0f / 128.0f);
        MS[tid] = m;
        RS[tid] = rsqrtf(fmaxf(sq * (1.0f / 128.0f) - m * m, 0.f) + 1e-5f);
    }
    __syncthreads();

    // normalize in place
    {
        float mp = MS[p], rp = RS[p];
#pragma unroll 4
        for (int cc = 0; cc < 32; ++cc) {
            int c = ch * 32 + cc;
            float lw = __ldg(lnw + c), lb = __ldg(lnb + c);
            As[c * 72 + p] = tf32r((As[c * 72 + p] - mp) * rp * lw + lb);
        }
    }

    const float2* Wc2 = (const float2*)Wc;
    const int boff0 = (n0 + g) * 68 + t;
    const int r = m0 + g;

#pragma unroll 1
    for (int cb = 0; cb < 128; cb += 64) {
        __syncthreads();
        loadWc(Wc, 5, cb, tid);
        __syncthreads();

        float acc[4][4];
#pragma unroll
        for (int i = 0; i < 4; ++i)
#pragma unroll
            for (int q = 0; q < 4; ++q) acc[i][q] = 0.f;

#pragma unroll
        for (int ks = 0; ks < 16; ++ks) {
            const int k0 = ks * 8;
            const float* ap = As + (k0 + t) * 72 + m0 + g;
            u32 aa[4] = { __float_as_uint(ap[0]),      __float_as_uint(ap[8]),
                          __float_as_uint(ap[4 * 72]), __float_as_uint(ap[4 * 72 + 8]) };
#pragma unroll
            for (int nt = 0; nt < 4; ++nt) {
                float2 b = Wc2[boff0 + nt * 8 * 68 + ks * 4];
                u32 bb[2] = { __float_as_uint(b.x), __float_as_uint(b.y) };
                mma8(acc[nt], aa, bb);
            }
        }

#pragma unroll
        for (int nt = 0; nt < 4; ++nt) {
            int c = cb + n0 + nt * 8 + 2 * t;
            float2 bzv = *(const float2*)(bz + c);
            float2 gv0 = *(const float2*)(g_G + (pair0 + r) * (size_t)CZ + c);
            float2 gv1 = *(const float2*)(g_G + (pair0 + r + 8) * (size_t)CZ + c);
            *(float2*)(out + (pair0 + r) * (size_t)CZ + c) =
                make_float2(gv0.x * (acc[nt][0] + bzv.x), gv0.y * (acc[nt][1] + bzv.y));
            *(float2*)(out + (pair0 + r + 8) * (size_t)CZ + c) =
                make_float2(gv1.x * (acc[nt][2] + bzv.x), gv1.y * (acc[nt][3] + bzv.y));
        }
    }
}

// ============================================================================
// kernel_launch — graph-capturable fork: proj_g runs concurrently with tri.
// ============================================================================
extern "C" void kernel_launch(void* const* d_in, const int* in_sizes, int n_in,
                              void* d_out, int out_size)
{
    const float* z        = (const float*)d_in[0];
    const float* ln_in_w  = (const float*)d_in[1];
    const float* ln_in_b  = (const float*)d_in[2];
    const float* ln_out_w = (const float*)d_in[3];
    const float* ln_out_b = (const float*)d_in[4];
    const float* w_ap     = (const float*)d_in[5];
    const float* b_ap     = (const float*)d_in[6];
    const float* w_ag     = (const float*)d_in[7];
    const float* b_ag     = (const float*)d_in[8];
    const float* w_bp     = (const float*)d_in[9];
    const float* b_bp     = (const float*)d_in[10];
    const float* w_bg     = (const float*)d_in[11];
    const float* b_bg     = (const float*)d_in[12];
    const float* w_g      = (const float*)d_in[13];
    const float* b_g      = (const float*)d_in[14];
    const float* w_z      = (const float*)d_in[15];
    const float* b_z      = (const float*)d_in[16];
    float* out = (float*)d_out;

    const int PROJ_SMEM = 2 * 64 * 136 * 4;                    // 69632
    const int TRI_SMEM  = 2 * 10240 * 4;                       // 81920
    const int FIN_SMEM  = (128 * 72 + 64 * 136 + 640) * 4;     // 74240

    static cudaStream_t s2 = nullptr;
    static cudaEvent_t ev_fork = nullptr, ev_join = nullptr;
    if (s2 == nullptr) {
        cudaStreamCreateWithFlags(&s2, cudaStreamNonBlocking);
        cudaEventCreateWithFlags(&ev_fork, cudaEventDisableTiming);
        cudaEventCreateWithFlags(&ev_join, cudaEventDisableTiming);
        cudaFuncSetAttribute(proj_ab_kernel, cudaFuncAttributeMaxDynamicSharedMemorySize, PROJ_SMEM);
        cudaFuncSetAttribute(proj_g_kernel,  cudaFuncAttributeMaxDynamicSharedMemorySize, PROJ_SMEM);
        cudaFuncSetAttribute(tri_kernel,     cudaFuncAttributeMaxDynamicSharedMemorySize, TRI_SMEM);
        cudaFuncSetAttribute(final_kernel,   cudaFuncAttributeMaxDynamicSharedMemorySize, FIN_SMEM);
    }

    dim3 pgrid(64, 6);
    prep_w<<<pgrid, 256>>>(w_ap, w_ag, w_bp, w_bg, w_g, w_z);

    proj_ab_kernel<<<NPAIR / 64, 256, PROJ_SMEM>>>(
        z, ln_in_w, ln_in_b, b_ap, b_ag, b_bp, b_bg);

    // fork: proj_g (stream s2) runs concurrently with tri (stream 0)
    cudaEventRecord(ev_fork, 0);
    cudaStreamWaitEvent(s2, ev_fork, 0);

    proj_g_kernel<<<NPAIR / 64, 256, PROJ_SMEM, s2>>>(z, ln_in_w, ln_in_b, b_g);

    dim3 tgrid(4, 4, 128);
    tri_kernel<<<tgrid, 256, TRI_SMEM>>>();

    // join
    cudaEventRecord(ev_join, s2);
    cudaStreamWaitEvent(0, ev_join, 0);

    final_kernel<<<NPAIR / 64, 256, FIN_SMEM>>>(ln_out_w, ln_out_b, b_z, out);
}

// round 11
// speedup vs baseline: 1.0381x; 1.0381x over previous
#include <cuda_runtime.h>
#include <math.h>

#define NROW 512
#define CZ   128
#define NPAIR (NROW * NROW) /* 262144 */

typedef unsigned int u32;

// ---------------- device scratch ----------------
__device__ float g_A[(size_t)CZ * NPAIR];   // a, [c][i*512 + kperm]
__device__ float g_B[(size_t)CZ * NPAIR];   // b, [c][j*512 + kperm]
__device__ float g_G[(size_t)NPAIR * CZ];   // gate, [pair][cz]  (natural)
__device__ float g_T[(size_t)CZ * NPAIR];   // t, [c][i*512+j]
__device__ float g_wt[6 * 128 * 128];       // weights, pair layout [n][128]
// img order: 0 w_ap, 1 w_ag, 2 w_bp, 3 w_bg, 4 w_g, 5 w_z

// ---------------- helpers ----------------
__device__ __forceinline__ float tf32r(float x) {
    float r;
    asm("cvt.rna.tf32.f32 %0, %1;" : "=f"(r) : "f"(x));
    return r;
}
__device__ __forceinline__ float wsum(float v) {
#pragma unroll
    for (int o = 16; o; o >>= 1) v += __shfl_xor_sync(0xffffffffu, v, o);
    return v;
}
__device__ __forceinline__ float sigm(float x) {
    return 1.0f / (1.0f + __expf(-x));
}
__device__ __forceinline__ void mma8(float* d, const u32* a, const u32* b) {
    asm volatile(
        "mma.sync.aligned.m16n8k8.row.col.f32.tf32.tf32.f32 "
        "{%0,%1,%2,%3}, {%4,%5,%6,%7}, {%8,%9}, {%0,%1,%2,%3};"
        : "+f"(d[0]), "+f"(d[1]), "+f"(d[2]), "+f"(d[3])
        : "r"(a[0]), "r"(a[1]), "r"(a[2]), "r"(a[3]), "r"(b[0]), "r"(b[1]));
}
__device__ __forceinline__ u32 smem_u32(const void* p) {
    u32 a;
    asm("{ .reg .u64 t; cvta.to.shared.u64 t, %1; cvt.u32.u64 %0, t; }" : "=r"(a) : "l"(p));
    return a;
}
__device__ __forceinline__ void cpa16(u32 dst, const void* src) {
    asm volatile("cp.async.cg.shared.global [%0], [%1], 16;" :: "r"(dst), "l"(src));
}
#define CP_COMMIT() asm volatile("cp.async.commit_group;" ::: "memory")
#define CP_WAIT(n)  asm volatile("cp.async.wait_group %0;" :: "n"(n) : "memory")

// ============================================================================
// prep: transpose + tf32-round weights into pair layout:
// g_wt[img][n*128 + (k>>3)*8 + (k&3)*2 + ((k&4)>>2)]
// ============================================================================
__global__ void prep_w(const float* __restrict__ wap, const float* __restrict__ wag,
                       const float* __restrict__ wbp, const float* __restrict__ wbg,
                       const float* __restrict__ wg,  const float* __restrict__ wz) {
    int img = blockIdx.y;
    int lin = blockIdx.x * 256 + threadIdx.x;
    int n = lin >> 7, k = lin & 127;
    const float* s;
    switch (img) {
        case 0: s = wap; break; case 1: s = wag; break;
        case 2: s = wbp; break; case 3: s = wbg; break;
        case 4: s = wg;  break; default: s = wz; break;
    }
    int pos = n * 128 + (k >> 3) * 8 + (k & 3) * 2 + ((k & 4) >> 2);
    g_wt[img * 16384 + pos] = tf32r(s[k * 128 + n]);
}

// ============================================================================
// load a 64-row weight chunk (rows nb..nb+63 of image img) into Wc
// ============================================================================
__device__ __forceinline__ void loadWc(float* __restrict__ Wc, int img, int nb, int tid) {
    const float4* src = (const float4*)(g_wt + img * 16384);
#pragma unroll
    for (int it = 0; it < 8; ++it) {
        int lin = it * 256 + tid;          // 0..2047
        int row = lin >> 5, q = lin & 31;
        ((float4*)Wc)[row * 34 + q] = src[(nb + row) * 32 + q];
    }
}

// ============================================================================
// GEMM: warp tile m32 x n32, K=128. As pair layout (stride 68 f2, 128 rows),
// Wc pair layout (64 rows, stride 68 f2). acc[2][4][4].
// ============================================================================
__device__ __forceinline__ void gemm32x32(const float2* __restrict__ As2,
                                          const float2* __restrict__ Wc2,
                                          int aoff, int boff0, float acc[2][4][4]) {
#pragma unroll
    for (int m = 0; m < 2; ++m)
#pragma unroll
        for (int i = 0; i < 4; ++i)
#pragma unroll
            for (int q = 0; q < 4; ++q) acc[m][i][q] = 0.f;
#pragma unroll
    for (int ks = 0; ks < 16; ++ks) {
        float2 a00 = As2[aoff + ks * 4];
        float2 a01 = As2[aoff + ks * 4 + 544];    // +8 rows
        float2 a10 = As2[aoff + ks * 4 + 1088];   // +16 rows
        float2 a11 = As2[aoff + ks * 4 + 1632];   // +24 rows
        u32 aa0[4] = { __float_as_uint(a00.x), __float_as_uint(a01.x),
                       __float_as_uint(a00.y), __float_as_uint(a01.y) };
        u32 aa1[4] = { __float_as_uint(a10.x), __float_as_uint(a11.x),
                       __float_as_uint(a10.y), __float_as_uint(a11.y) };
#pragma unroll
        for (int nt = 0; nt < 4; ++nt) {
            float2 b = Wc2[boff0 + nt * 8 * 68 + ks * 4];
            u32 bb[2] = { __float_as_uint(b.x), __float_as_uint(b.y) };
            mma8(acc[0][nt], aa0, bb);
            mma8(acc[1][nt], aa1, bb);
        }
    }
}

// GEMM: warp tile m16 x n32 (for proj_g, 64-pair tiles). acc[4][4].
__device__ __forceinline__ void gemm32(const float2* __restrict__ As2,
                                       const float2* __restrict__ Wc2,
                                       int aoff, int boff0, float acc[4][4]) {
#pragma unroll
    for (int i = 0; i < 4; ++i)
#pragma unroll
        for (int q = 0; q < 4; ++q) acc[i][q] = 0.f;
#pragma unroll
    for (int ks = 0; ks < 16; ++ks) {
        float2 a0 = As2[aoff + ks * 4];
        float2 a1 = As2[aoff + ks * 4 + 544];   // +8 rows
        u32 aa[4] = { __float_as_uint(a0.x), __float_as_uint(a1.x),
                      __float_as_uint(a0.y), __float_as_uint(a1.y) };
#pragma unroll
        for (int nt = 0; nt < 4; ++nt) {
            float2 b = Wc2[boff0 + nt * 8 * 68 + ks * 4];
            u32 bb[2] = { __float_as_uint(b.x), __float_as_uint(b.y) };
            mma8(acc[nt], aa, bb);
        }
    }
}

// ============================================================================
// proj_ab: 128-pair tiles, warp tile m32n32 (1.0 LDS/MMA), 8 GEMM passes
// -> g_A, g_B (k-permuted rows). smem = As(128x136)+Wc(64x136) = 104448B
// -> 2 CTAs/SM.
// ============================================================================
__global__ __launch_bounds__(256, 2) void proj_ab_kernel(
    const float* __restrict__ z,
    const float* __restrict__ lnw, const float* __restrict__ lnb,
    const float* __restrict__ b_ap, const float* __restrict__ b_ag,
    const float* __restrict__ b_bp, const float* __restrict__ b_bg)
{
    extern __shared__ float smf[];
    float* As = smf;                 // 128 x 136
    float* Wc = smf + 128 * 136;     // 64 x 136
    const int tid = threadIdx.x;
    const int wid = tid >> 5, lane = tid & 31;
    const int g = lane >> 2, t = lane & 3;
    const int m0 = (wid & 3) * 32, n0 = (wid >> 2) * 32;
    const size_t pair0 = (size_t)blockIdx.x * 128;

    // ---- LN -> As (pair layout); warp handles 16 rows ----
    {
        float4 lw = ((const float4*)lnw)[lane];
        float4 lb = ((const float4*)lnb)[lane];
#pragma unroll 2
        for (int r = 0; r < 16; ++r) {
            int row = wid * 16 + r;
            float4 x = ((const float4*)(z + (pair0 + row) * (size_t)CZ))[lane];
            float m = wsum(x.x + x.y + x.z + x.w) * (1.0f / 128.0f);
            float dx = x.x - m, dy = x.y - m, dz = x.z - m, dw = x.w - m;
            float var = wsum(dx * dx + dy * dy + dz * dz + dw * dw) * (1.0f / 128.0f);
            float rs = rsqrtf(var + 1e-5f);
            float* dst = As + row * 136 + (lane >> 1) * 8 + (lane & 1);
            dst[0] = tf32r(dx * rs * lw.x + lb.x);
            dst[2] = tf32r(dy * rs * lw.y + lb.y);
            dst[4] = tf32r(dz * rs * lw.z + lb.z);
            dst[6] = tf32r(dw * rs * lw.w + lb.w);
        }
    }

    const float2* As2 = (const float2*)As;
    const float2* Wc2 = (const float2*)Wc;
    const int aoff = (m0 + g) * 68 + t;
    const int boff0 = (n0 + g) * 68 + t;
    // permuted rows for the two m16 subtiles
    const int rp0 = m0 + (g & 3) * 2 + (g >> 2);
    const int rp1 = m0 + 16 + (g & 3) * 2 + (g >> 2);

    float accg[2][4][4], accp[2][4][4];

#pragma unroll 1
    for (int sel = 0; sel < 2; ++sel) {
        const int imgP = sel * 2, imgG = sel * 2 + 1;
        const float* bp = sel ? b_bp : b_ap;
        const float* bg = sel ? b_bg : b_ag;
        float* __restrict__ dst = sel ? g_B : g_A;
#pragma unroll 1
        for (int cb = 0; cb < 128; cb += 64) {
            __syncthreads();
            loadWc(Wc, imgG, cb, tid);
            __syncthreads();
            gemm32x32(As2, Wc2, aoff, boff0, accg);
            __syncthreads();
            loadWc(Wc, imgP, cb, tid);
            __syncthreads();
            gemm32x32(As2, Wc2, aoff, boff0, accp);
#pragma unroll
            for (int mt = 0; mt < 2; ++mt) {
                const int rp = mt ? rp1 : rp0;
#pragma unroll
                for (int nt = 0; nt < 4; ++nt) {
                    int c = cb + n0 + nt * 8 + 2 * t;
                    float2 bpv = *(const float2*)(bp + c);
                    float2 bgv = *(const float2*)(bg + c);
                    float* d0 = dst + (size_t)c * NPAIR + pair0;
                    float* d1 = dst + (size_t)(c + 1) * NPAIR + pair0;
                    const float* P = accp[mt][nt];
                    const float* G = accg[mt][nt];
                    d0[rp]     = tf32r(sigm(G[0] + bgv.x) * (P[0] + bpv.x));
                    d1[rp]     = tf32r(sigm(G[1] + bgv.y) * (P[1] + bpv.y));
                    d0[rp + 8] = tf32r(sigm(G[2] + bgv.x) * (P[2] + bpv.x));
                    d1[rp + 8] = tf32r(sigm(G[3] + bgv.y) * (P[3] + bpv.y));
                }
            }
        }
    }
}

// ============================================================================
// proj_g: 64-pair tiles, LN + 2 GEMM passes -> g_G (natural [pair][cz]).
// smem = 2 x 64x136 = 69632B -> 3 CTAs/SM.
// ============================================================================
__global__ __launch_bounds__(256, 3) void proj_g_kernel(
    const float* __restrict__ z,
    const float* __restrict__ lnw, const float* __restrict__ lnb,
    const float* __restrict__ b_g)
{
    extern __shared__ float smf[];
    float* As = smf;                 // 64 x 136
    float* Wc = smf + 64 * 136;      // 64 x 136
    const int tid = threadIdx.x;
    const int wid = tid >> 5, lane = tid & 31;
    const int g = lane >> 2, t = lane & 3;
    const int m0 = (wid & 3) * 16, n0 = (wid >> 2) * 32;
    const size_t pair0 = (size_t)blockIdx.x * 64;

    // ---- LN -> As (pair layout); warp handles 8 rows ----
    {
        float4 lw = ((const float4*)lnw)[lane];
        float4 lb = ((const float4*)lnb)[lane];
#pragma unroll 2
        for (int r = 0; r < 8; ++r) {
            int row = wid * 8 + r;
            float4 x = ((const float4*)(z + (pair0 + row) * (size_t)CZ))[lane];
            float m = wsum(x.x + x.y + x.z + x.w) * (1.0f / 128.0f);
            float dx = x.x - m, dy = x.y - m, dz = x.z - m, dw = x.w - m;
            float var = wsum(dx * dx + dy * dy + dz * dz + dw * dw) * (1.0f / 128.0f);
            float rs = rsqrtf(var + 1e-5f);
            float* dst = As + row * 136 + (lane >> 1) * 8 + (lane & 1);
            dst[0] = tf32r(dx * rs * lw.x + lb.x);
            dst[2] = tf32r(dy * rs * lw.y + lb.y);
            dst[4] = tf32r(dz * rs * lw.z + lb.z);
            dst[6] = tf32r(dw * rs * lw.w + lb.w);
        }
    }

    const float2* As2 = (const float2*)As;
    const float2* Wc2 = (const float2*)Wc;
    const int aoff = (m0 + g) * 68 + t;
    const int boff0 = (n0 + g) * 68 + t;
    const int r = m0 + g;

    float accg[4][4];

#pragma unroll 1
    for (int cb = 0; cb < 128; cb += 64) {
        __syncthreads();
        loadWc(Wc, 4, cb, tid);
        __syncthreads();
        gemm32(As2, Wc2, aoff, boff0, accg);
#pragma unroll
        for (int nt = 0; nt < 4; ++nt) {
            int c = cb + n0 + nt * 8 + 2 * t;
            float2 bgv = *(const float2*)(b_g + c);
            *(float2*)(g_G + (pair0 + r) * (size_t)CZ + c) =
                make_float2(sigm(accg[nt][0] + bgv.x), sigm(accg[nt][1] + bgv.y));
            *(float2*)(g_G + (pair0 + r + 8) * (size_t)CZ + c) =
                make_float2(sigm(accg[nt][2] + bgv.x), sigm(accg[nt][3] + bgv.y));
        }
    }
}

// ============================================================================
// tri: t[c][i][j] = sum_k a[c][i][k]*b[c][j][k]; 128x128 tile, K chunks of 32,
// cp.async DOUBLE-buffered. smem 80KB -> 2 CTAs/SM.
// ============================================================================
__global__ __launch_bounds__(256, 2) void tri_kernel()
{
    extern __shared__ float smf[];   // [buf][A 5120 | B 5120] floats
    const int tid = threadIdx.x;
    const int wid = tid >> 5, lane = tid & 31;
    const int g = lane >> 2, t = lane & 3;
    const int m0 = (wid & 3) * 32, n0 = (wid >> 2) * 64;
    const int c  = blockIdx.z;
    const int i0 = blockIdx.y * 128;
    const int j0 = blockIdx.x * 128;
    const float* __restrict__ asrc = g_A + (size_t)c * NPAIR + (size_t)i0 * NROW;
    const float* __restrict__ bsrc = g_B + (size_t)c * NPAIR + (size_t)j0 * NROW;
    const u32 smb = smem_u32(smf);

    auto issue = [&](int s) {
        const int k0 = s * 32;
        const u32 base = smb + (u32)(s & 1) * 10240u * 4u;
#pragma unroll
        for (int it = 0; it < 4; ++it) {
            int lin = it * 256 + tid;      // 0..1023
            int row = lin >> 3, j = lin & 7;
            u32 doff = (u32)(row * 40 + j * 4) * 4u;
            cpa16(base + doff, asrc + (size_t)row * NROW + k0 + j * 4);
            cpa16(base + 5120u * 4u + doff, bsrc + (size_t)row * NROW + k0 + j * 4);
        }
    };

    float acc[2][8][4];
#pragma unroll
    for (int i = 0; i < 2; ++i)
#pragma unroll
        for (int j = 0; j < 8; ++j)
#pragma unroll
            for (int q = 0; q < 4; ++q) acc[i][j][q] = 0.f;

    const int aoff = (m0 + g) * 20 + t;
    int boff[8];
#pragma unroll
    for (int nt = 0; nt < 8; ++nt) boff[nt] = (n0 + nt * 8 + g) * 20 + t;

    issue(0); CP_COMMIT();

#pragma unroll 1
    for (int kc = 0; kc < 16; ++kc) {
        if (kc < 15) { issue(kc + 1); CP_COMMIT(); CP_WAIT(1); }
        else         { CP_WAIT(0); }
        __syncthreads();

        const float2* A2 = (const float2*)(smf + (kc & 1) * 10240);
        const float2* B2 = (const float2*)(smf + (kc & 1) * 10240 + 5120);
#pragma unroll
        for (int ks = 0; ks < 4; ++ks) {
            float2 a00 = A2[aoff + ks * 4];
            float2 a01 = A2[aoff + ks * 4 + 160];
            float2 a10 = A2[aoff + ks * 4 + 320];
            float2 a11 = A2[aoff + ks * 4 + 480];
            u32 aa0[4] = { __float_as_uint(a00.x), __float_as_uint(a01.x),
                           __float_as_uint(a00.y), __float_as_uint(a01.y) };
            u32 aa1[4] = { __float_as_uint(a10.x), __float_as_uint(a11.x),
                           __float_as_uint(a10.y), __float_as_uint(a11.y) };
#pragma unroll
            for (int nt = 0; nt < 8; ++nt) {
                float2 b = B2[boff[nt] + ks * 4];
                u32 bb[2] = { __float_as_uint(b.x), __float_as_uint(b.y) };
                mma8(acc[0][nt], aa0, bb);
                mma8(acc[1][nt], aa1, bb);
            }
        }
        __syncthreads();
    }

    float* __restrict__ tdst = g_T + (size_t)c * NPAIR;
#pragma unroll
    for (int mt = 0; mt < 2; ++mt) {
        int r = i0 + m0 + mt * 16 + g;
#pragma unroll
        for (int nt = 0; nt < 8; ++nt) {
            int cl = j0 + n0 + nt * 8 + 2 * t;
            *(float2*)(tdst + (size_t)r * NROW + cl) =
                make_float2(acc[mt][nt][0], acc[mt][nt][1]);
            *(float2*)(tdst + (size_t)(r + 8) * NROW + cl) =
                make_float2(acc[mt][nt][2], acc[mt][nt][3]);
        }
    }
}

// ============================================================================
// final: out[pair][cz] = g * (LN_c(t) @ Wz + bz). 64-pair tiles, grid 4096.
// t gathered via cp.async; gate in natural layout (coalesced with out).
// smem = As(128x72) + Wc(64x136) + stats = 74240B -> 3 CTAs/SM.
// ============================================================================
__global__ __launch_bounds__(256, 3) void final_kernel(
    const float* __restrict__ lnw, const float* __restrict__ lnb,
    const float* __restrict__ bz, float* __restrict__ out)
{
    extern __shared__ float smf[];
    float* As = smf;                 // [128 c][72 pair] k-major
    float* Wc = As + 128 * 72;       // 64 x 136
    float* PS = Wc + 64 * 136;       // 256
    float* PQ = PS + 256;            // 256
    float* MS = PQ + 256;            // 64
    float* RS = MS + 64;             // 64
    const int tid = threadIdx.x;
    const int wid = tid >> 5, lane = tid & 31;
    const int g = lane >> 2, t = lane & 3;
    const int m0 = (wid & 3) * 16, n0 = (wid >> 2) * 32;
    const int p = tid & 63, ch = tid >> 6;
    const size_t pair0 = (size_t)blockIdx.x * 64;
    const u32 smb = smem_u32(smf);

    // ---- async gather of t: 2048 x 16B ----
#pragma unroll
    for (int it = 0; it < 8; ++it) {
        int lin = it * 256 + tid;        // 0..2047
        int c = lin >> 4, p4 = lin & 15;
        cpa16(smb + (u32)(c * 72 + p4 * 4) * 4u,
              g_T + (size_t)c * NPAIR + pair0 + p4 * 4);
    }
    CP_COMMIT();
    CP_WAIT(0);
    __syncthreads();

    // ---- stats from smem ----
    {
        float s = 0.f, qq = 0.f;
#pragma unroll 4
        for (int cc = 0; cc < 32; ++cc) {
            int c = ch * 32 + cc;
            float v = As[c * 72 + p];
            s += v; qq += v * v;
        }
        PS[tid] = s; PQ[tid] = qq;
    }
    __syncthreads();
    if (tid < 64) {
        float ss = PS[tid] + PS[tid + 64] + PS[tid + 128] + PS[tid + 192];
        float sq = PQ[tid] + PQ[tid + 64] + PQ[tid + 128] + PQ[tid + 192];
        float m = ss * (1.0f / 128.0f);
        MS[tid] = m;
        RS[tid] = rsqrtf(fmaxf(sq * (1.0f / 128.0f) - m * m, 0.f) + 1e-5f);
    }
    __syncthreads();

    // normalize in place
    {
        float mp = MS[p], rp = RS[p];
#pragma unroll 4
        for (int cc = 0; cc < 32; ++cc) {
            int c = ch * 32 + cc;
            float lw = __ldg(lnw + c), lb = __ldg(lnb + c);
            As[c * 72 + p] = tf32r((As[c * 72 + p] - mp) * rp * lw + lb);
        }
    }

    const float2* Wc2 = (const float2*)Wc;
    const int boff0 = (n0 + g) * 68 + t;
    const int r = m0 + g;

#pragma unroll 1
    for (int cb = 0; cb < 128; cb += 64) {
        __syncthreads();
        loadWc(Wc, 5, cb, tid);
        __syncthreads();

        float acc[4][4];
#pragma unroll
        for (int i = 0; i < 4; ++i)
#pragma unroll
            for (int q = 0; q < 4; ++q) acc[i][q] = 0.f;

#pragma unroll
        for (int ks = 0; ks < 16; ++ks) {
            const int k0 = ks * 8;
            const float* ap = As + (k0 + t) * 72 + m0 + g;
            u32 aa[4] = { __float_as_uint(ap[0]),      __float_as_uint(ap[8]),
                          __float_as_uint(ap[4 * 72]), __float_as_uint(ap[4 * 72 + 8]) };
#pragma unroll
            for (int nt = 0; nt < 4; ++nt) {
                float2 b = Wc2[boff0 + nt * 8 * 68 + ks * 4];
                u32 bb[2] = { __float_as_uint(b.x), __float_as_uint(b.y) };
                mma8(acc[nt], aa, bb);
            }
        }

#pragma unroll
        for (int nt = 0; nt < 4; ++nt) {
            int c = cb + n0 + nt * 8 + 2 * t;
            float2 bzv = *(const float2*)(bz + c);
            float2 gv0 = *(const float2*)(g_G + (pair0 + r) * (size_t)CZ + c);
            float2 gv1 = *(const float2*)(g_G + (pair0 + r + 8) * (size_t)CZ + c);
            *(float2*)(out + (pair0 + r) * (size_t)CZ + c) =
                make_float2(gv0.x * (acc[nt][0] + bzv.x), gv0.y * (acc[nt][1] + bzv.y));
            *(float2*)(out + (pair0 + r + 8) * (size_t)CZ + c) =
                make_float2(gv1.x * (acc[nt][2] + bzv.x), gv1.y * (acc[nt][3] + bzv.y));
        }
    }
}

// ============================================================================
// kernel_launch — sequential, single stream (fork reverted)
// ============================================================================
extern "C" void kernel_launch(void* const* d_in, const int* in_sizes, int n_in,
                              void* d_out, int out_size)
{
    const float* z        = (const float*)d_in[0];
    const float* ln_in_w  = (const float*)d_in[1];
    const float* ln_in_b  = (const float*)d_in[2];
    const float* ln_out_w = (const float*)d_in[3];
    const float* ln_out_b = (const float*)d_in[4];
    const float* w_ap     = (const float*)d_in[5];
    const float* b_ap     = (const float*)d_in[6];
    const float* w_ag     = (const float*)d_in[7];
    const float* b_ag     = (const float*)d_in[8];
    const float* w_bp     = (const float*)d_in[9];
    const float* b_bp     = (const float*)d_in[10];
    const float* w_bg     = (const float*)d_in[11];
    const float* b_bg     = (const float*)d_in[12];
    const float* w_g      = (const float*)d_in[13];
    const float* b_g      = (const float*)d_in[14];
    const float* w_z      = (const float*)d_in[15];
    const float* b_z      = (const float*)d_in[16];
    float* out = (float*)d_out;

    const int PAB_SMEM  = (128 * 136 + 64 * 136) * 4;          // 104448
    const int PG_SMEM   = 2 * 64 * 136 * 4;                    // 69632
    const int TRI_SMEM  = 2 * 10240 * 4;                       // 81920
    const int FIN_SMEM  = (128 * 72 + 64 * 136 + 640) * 4;     // 74240

    cudaFuncSetAttribute(proj_ab_kernel, cudaFuncAttributeMaxDynamicSharedMemorySize, PAB_SMEM);
    cudaFuncSetAttribute(proj_g_kernel,  cudaFuncAttributeMaxDynamicSharedMemorySize, PG_SMEM);
    cudaFuncSetAttribute(tri_kernel,     cudaFuncAttributeMaxDynamicSharedMemorySize, TRI_SMEM);
    cudaFuncSetAttribute(final_kernel,   cudaFuncAttributeMaxDynamicSharedMemorySize, FIN_SMEM);

    dim3 pgrid(64, 6);
    prep_w<<<pgrid, 256>>>(w_ap, w_ag, w_bp, w_bg, w_g, w_z);

    proj_ab_kernel<<<NPAIR / 128, 256, PAB_SMEM>>>(
        z, ln_in_w, ln_in_b, b_ap, b_ag, b_bp, b_bg);
    proj_g_kernel<<<NPAIR / 64, 256, PG_SMEM>>>(z, ln_in_w, ln_in_b, b_g);

    dim3 tgrid(4, 4, 128);
    tri_kernel<<<tgrid, 256, TRI_SMEM>>>();

    final_kernel<<<NPAIR / 64, 256, FIN_SMEM>>>(ln_out_w, ln_out_b, b_z, out);
}

// round 12
// speedup vs baseline: 1.1101x; 1.0694x over previous
#include <cuda_runtime.h>
#include <math.h>

#define NROW 512
#define CZ   128
#define NPAIR (NROW * NROW) /* 262144 */

typedef unsigned int u32;

// ---------------- device scratch ----------------
__device__ float g_A[(size_t)CZ * NPAIR];   // a, [c][i*512 + kperm]
__device__ float g_B[(size_t)CZ * NPAIR];   // b, [c][j*512 + kperm]
__device__ float g_G[(size_t)NPAIR * CZ];   // gate, [pair][cz]  (natural)
__device__ float g_T[(size_t)CZ * NPAIR];   // t, [c][i*512+j]
__device__ float g_wt[6 * 128 * 128];       // weights, pair layout [n][128]
// img order: 0 w_ap, 1 w_ag, 2 w_bp, 3 w_bg, 4 w_g, 5 w_z

// ---------------- helpers ----------------
__device__ __forceinline__ float tf32r(float x) {
    float r;
    asm("cvt.rna.tf32.f32 %0, %1;" : "=f"(r) : "f"(x));
    return r;
}
__device__ __forceinline__ float wsum(float v) {
#pragma unroll
    for (int o = 16; o; o >>= 1) v += __shfl_xor_sync(0xffffffffu, v, o);
    return v;
}
__device__ __forceinline__ float sigm(float x) {
    return 1.0f / (1.0f + __expf(-x));
}
__device__ __forceinline__ void mma8(float* d, const u32* a, const u32* b) {
    asm volatile(
        "mma.sync.aligned.m16n8k8.row.col.f32.tf32.tf32.f32 "
        "{%0,%1,%2,%3}, {%4,%5,%6,%7}, {%8,%9}, {%0,%1,%2,%3};"
        : "+f"(d[0]), "+f"(d[1]), "+f"(d[2]), "+f"(d[3])
        : "r"(a[0]), "r"(a[1]), "r"(a[2]), "r"(a[3]), "r"(b[0]), "r"(b[1]));
}
__device__ __forceinline__ u32 smem_u32(const void* p) {
    u32 a;
    asm("{ .reg .u64 t; cvta.to.shared.u64 t, %1; cvt.u32.u64 %0, t; }" : "=r"(a) : "l"(p));
    return a;
}
__device__ __forceinline__ void cpa16(u32 dst, const void* src) {
    asm volatile("cp.async.cg.shared.global [%0], [%1], 16;" :: "r"(dst), "l"(src));
}
#define CP_COMMIT() asm volatile("cp.async.commit_group;" ::: "memory")
#define CP_WAIT(n)  asm volatile("cp.async.wait_group %0;" :: "n"(n) : "memory")

// ============================================================================
// prep: transpose + tf32-round weights into pair layout:
// g_wt[img][n*128 + (k>>3)*8 + (k&3)*2 + ((k&4)>>2)]
// ============================================================================
__global__ void prep_w(const float* __restrict__ wap, const float* __restrict__ wag,
                       const float* __restrict__ wbp, const float* __restrict__ wbg,
                       const float* __restrict__ wg,  const float* __restrict__ wz) {
    int img = blockIdx.y;
    int lin = blockIdx.x * 256 + threadIdx.x;
    int n = lin >> 7, k = lin & 127;
    const float* s;
    switch (img) {
        case 0: s = wap; break; case 1: s = wag; break;
        case 2: s = wbp; break; case 3: s = wbg; break;
        case 4: s = wg;  break; default: s = wz; break;
    }
    int pos = n * 128 + (k >> 3) * 8 + (k & 3) * 2 + ((k & 4) >> 2);
    g_wt[img * 16384 + pos] = tf32r(s[k * 128 + n]);
}

// ============================================================================
// load a 64-row weight chunk (rows nb..nb+63 of image img) into Wc
// ============================================================================
__device__ __forceinline__ void loadWc(float* __restrict__ Wc, int img, int nb, int tid) {
    const float4* src = (const float4*)(g_wt + img * 16384);
#pragma unroll
    for (int it = 0; it < 8; ++it) {
        int lin = it * 256 + tid;          // 0..2047
        int row = lin >> 5, q = lin & 31;
        ((float4*)Wc)[row * 34 + q] = src[(nb + row) * 32 + q];
    }
}

// ============================================================================
// GEMM: warp tile m32 x n32, K=128. As pair layout (stride 68 f2, 128 rows),
// Wc pair layout (64 rows, stride 68 f2). acc[2][4][4].
// ============================================================================
__device__ __forceinline__ void gemm32x32(const float2* __restrict__ As2,
                                          const float2* __restrict__ Wc2,
                                          int aoff, int boff0, float acc[2][4][4]) {
#pragma unroll
    for (int m = 0; m < 2; ++m)
#pragma unroll
        for (int i = 0; i < 4; ++i)
#pragma unroll
            for (int q = 0; q < 4; ++q) acc[m][i][q] = 0.f;
#pragma unroll
    for (int ks = 0; ks < 16; ++ks) {
        float2 a00 = As2[aoff + ks * 4];
        float2 a01 = As2[aoff + ks * 4 + 544];    // +8 rows
        float2 a10 = As2[aoff + ks * 4 + 1088];   // +16 rows
        float2 a11 = As2[aoff + ks * 4 + 1632];   // +24 rows
        u32 aa0[4] = { __float_as_uint(a00.x), __float_as_uint(a01.x),
                       __float_as_uint(a00.y), __float_as_uint(a01.y) };
        u32 aa1[4] = { __float_as_uint(a10.x), __float_as_uint(a11.x),
                       __float_as_uint(a10.y), __float_as_uint(a11.y) };
#pragma unroll
        for (int nt = 0; nt < 4; ++nt) {
            float2 b = Wc2[boff0 + nt * 8 * 68 + ks * 4];
            u32 bb[2] = { __float_as_uint(b.x), __float_as_uint(b.y) };
            mma8(acc[0][nt], aa0, bb);
            mma8(acc[1][nt], aa1, bb);
        }
    }
}

// ============================================================================
// proj_all: FUSED. 128-pair tiles, warp tile m32n32, LN once, then
// ap||ag -> g_A, bp||bg -> g_B (k-permuted rows), g -> g_G (natural).
// smem = As(128x136)+Wc(64x136) = 104448B -> 2 CTAs/SM.
// ============================================================================
__global__ __launch_bounds__(256, 2) void proj_all_kernel(
    const float* __restrict__ z,
    const float* __restrict__ lnw, const float* __restrict__ lnb,
    const float* __restrict__ b_ap, const float* __restrict__ b_ag,
    const float* __restrict__ b_bp, const float* __restrict__ b_bg,
    const float* __restrict__ b_g)
{
    extern __shared__ float smf[];
    float* As = smf;                 // 128 x 136
    float* Wc = smf + 128 * 136;     // 64 x 136
    const int tid = threadIdx.x;
    const int wid = tid >> 5, lane = tid & 31;
    const int g = lane >> 2, t = lane & 3;
    const int m0 = (wid & 3) * 32, n0 = (wid >> 2) * 32;
    const size_t pair0 = (size_t)blockIdx.x * 128;

    // ---- LN -> As (pair layout); warp handles 16 rows ----
    {
        float4 lw = ((const float4*)lnw)[lane];
        float4 lb = ((const float4*)lnb)[lane];
#pragma unroll 2
        for (int r = 0; r < 16; ++r) {
            int row = wid * 16 + r;
            float4 x = ((const float4*)(z + (pair0 + row) * (size_t)CZ))[lane];
            float m = wsum(x.x + x.y + x.z + x.w) * (1.0f / 128.0f);
            float dx = x.x - m, dy = x.y - m, dz = x.z - m, dw = x.w - m;
            float var = wsum(dx * dx + dy * dy + dz * dz + dw * dw) * (1.0f / 128.0f);
            float rs = rsqrtf(var + 1e-5f);
            float* dst = As + row * 136 + (lane >> 1) * 8 + (lane & 1);
            dst[0] = tf32r(dx * rs * lw.x + lb.x);
            dst[2] = tf32r(dy * rs * lw.y + lb.y);
            dst[4] = tf32r(dz * rs * lw.z + lb.z);
            dst[6] = tf32r(dw * rs * lw.w + lb.w);
        }
    }

    const float2* As2 = (const float2*)As;
    const float2* Wc2 = (const float2*)Wc;
    const int aoff = (m0 + g) * 68 + t;
    const int boff0 = (n0 + g) * 68 + t;
    // permuted rows for the two m16 subtiles (g_A/g_B)
    const int rp0 = m0 + (g & 3) * 2 + (g >> 2);
    const int rp1 = m0 + 16 + (g & 3) * 2 + (g >> 2);
    // natural rows (g_G)
    const int r0 = m0 + g, r1 = m0 + 16 + g;

    float accg[2][4][4], accp[2][4][4];

    // ---- a then b (k-permuted rows) ----
#pragma unroll 1
    for (int sel = 0; sel < 2; ++sel) {
        const int imgP = sel * 2, imgG = sel * 2 + 1;
        const float* bp = sel ? b_bp : b_ap;
        const float* bg = sel ? b_bg : b_ag;
        float* __restrict__ dst = sel ? g_B : g_A;
#pragma unroll 1
        for (int cb = 0; cb < 128; cb += 64) {
            __syncthreads();
            loadWc(Wc, imgG, cb, tid);
            __syncthreads();
            gemm32x32(As2, Wc2, aoff, boff0, accg);
            __syncthreads();
            loadWc(Wc, imgP, cb, tid);
            __syncthreads();
            gemm32x32(As2, Wc2, aoff, boff0, accp);
#pragma unroll
            for (int mt = 0; mt < 2; ++mt) {
                const int rp = mt ? rp1 : rp0;
#pragma unroll
                for (int nt = 0; nt < 4; ++nt) {
                    int c = cb + n0 + nt * 8 + 2 * t;
                    float2 bpv = *(const float2*)(bp + c);
                    float2 bgv = *(const float2*)(bg + c);
                    float* d0 = dst + (size_t)c * NPAIR + pair0;
                    float* d1 = dst + (size_t)(c + 1) * NPAIR + pair0;
                    const float* P = accp[mt][nt];
                    const float* G = accg[mt][nt];
                    d0[rp]     = tf32r(sigm(G[0] + bgv.x) * (P[0] + bpv.x));
                    d1[rp]     = tf32r(sigm(G[1] + bgv.y) * (P[1] + bpv.y));
                    d0[rp + 8] = tf32r(sigm(G[2] + bgv.x) * (P[2] + bpv.x));
                    d1[rp + 8] = tf32r(sigm(G[3] + bgv.y) * (P[3] + bpv.y));
                }
            }
        }
    }

    // ---- gate g (natural rows, float2 stores) ----
#pragma unroll 1
    for (int cb = 0; cb < 128; cb += 64) {
        __syncthreads();
        loadWc(Wc, 4, cb, tid);
        __syncthreads();
        gemm32x32(As2, Wc2, aoff, boff0, accg);
#pragma unroll
        for (int mt = 0; mt < 2; ++mt) {
            const int r = mt ? r1 : r0;
#pragma unroll
            for (int nt = 0; nt < 4; ++nt) {
                int c = cb + n0 + nt * 8 + 2 * t;
                float2 bgv = *(const float2*)(b_g + c);
                const float* G = accg[mt][nt];
                *(float2*)(g_G + (pair0 + r) * (size_t)CZ + c) =
                    make_float2(sigm(G[0] + bgv.x), sigm(G[1] + bgv.y));
                *(float2*)(g_G + (pair0 + r + 8) * (size_t)CZ + c) =
                    make_float2(sigm(G[2] + bgv.x), sigm(G[3] + bgv.y));
            }
        }
    }
}

// ============================================================================
// tri: t[c][i][j] = sum_k a[c][i][k]*b[c][j][k]; 128x128 tile, K chunks of 32,
// cp.async DOUBLE-buffered, kc unrolled x2 (compile-time buffer bases),
// hoisted copy offsets. smem 80KB -> 2 CTAs/SM.
// ============================================================================
__global__ __launch_bounds__(256, 2) void tri_kernel()
{
    extern __shared__ float smf[];   // [buf0: A 5120 | B 5120][buf1: A | B]
    const int tid = threadIdx.x;
    const int wid = tid >> 5, lane = tid & 31;
    const int g = lane >> 2, t = lane & 3;
    const int m0 = (wid & 3) * 32, n0 = (wid >> 2) * 64;
    const int c  = blockIdx.z;
    const int i0 = blockIdx.y * 128;
    const int j0 = blockIdx.x * 128;
    const float* __restrict__ asrc = g_A + (size_t)c * NPAIR + (size_t)i0 * NROW;
    const float* __restrict__ bsrc = g_B + (size_t)c * NPAIR + (size_t)j0 * NROW;
    const u32 smb = smem_u32(smf);

    // hoisted per-thread copy offsets
    int offg[4];      // gmem float offset (row*NROW + j*4)
    u32 offs[4];      // smem byte offset within a buffer
#pragma unroll
    for (int it = 0; it < 4; ++it) {
        int lin = it * 256 + tid, row = lin >> 3, j = lin & 7;
        offg[it] = row * NROW + j * 4;
        offs[it] = (u32)(row * 40 + j * 4) * 4u;
    }
    const u32 bufA0 = smb;
    const u32 bufB0 = smb + 5120u * 4u;
    const u32 bufA1 = smb + 10240u * 4u;
    const u32 bufB1 = smb + 15360u * 4u;

    float acc[2][8][4];
#pragma unroll
    for (int i = 0; i < 2; ++i)
#pragma unroll
        for (int j = 0; j < 8; ++j)
#pragma unroll
            for (int q = 0; q < 4; ++q) acc[i][j][q] = 0.f;

    const int aoff = (m0 + g) * 20 + t;
    int boff[8];
#pragma unroll
    for (int nt = 0; nt < 8; ++nt) boff[nt] = (n0 + nt * 8 + g) * 20 + t;

    auto issue2 = [&](u32 baseA, u32 baseB, int k0) {
#pragma unroll
        for (int it = 0; it < 4; ++it) {
            cpa16(baseA + offs[it], asrc + offg[it] + k0);
            cpa16(baseB + offs[it], bsrc + offg[it] + k0);
        }
    };

    auto compute = [&](const float2* __restrict__ A2, const float2* __restrict__ B2) {
#pragma unroll
        for (int ks = 0; ks < 4; ++ks) {
            float2 a00 = A2[aoff + ks * 4];
            float2 a01 = A2[aoff + ks * 4 + 160];
            float2 a10 = A2[aoff + ks * 4 + 320];
            float2 a11 = A2[aoff + ks * 4 + 480];
            u32 aa0[4] = { __float_as_uint(a00.x), __float_as_uint(a01.x),
                           __float_as_uint(a00.y), __float_as_uint(a01.y) };
            u32 aa1[4] = { __float_as_uint(a10.x), __float_as_uint(a11.x),
                           __float_as_uint(a10.y), __float_as_uint(a11.y) };
#pragma unroll
            for (int nt = 0; nt < 8; ++nt) {
                float2 b = B2[boff[nt] + ks * 4];
                u32 bb[2] = { __float_as_uint(b.x), __float_as_uint(b.y) };
                mma8(acc[0][nt], aa0, bb);
                mma8(acc[1][nt], aa1, bb);
            }
        }
    };

    issue2(bufA0, bufB0, 0); CP_COMMIT();

#pragma unroll 1
    for (int kc2 = 0; kc2 < 8; ++kc2) {
        const int kc = kc2 * 2;
        // phase 0: prefetch chunk kc+1 -> buf1, compute buf0
        issue2(bufA1, bufB1, (kc + 1) * 32); CP_COMMIT(); CP_WAIT(1);
        __syncthreads();
        compute((const float2*)smf, (const float2*)(smf + 5120));
        __syncthreads();
        // phase 1: prefetch chunk kc+2 -> buf0 (if any), compute buf1
        if (kc + 2 < 16) { issue2(bufA0, bufB0, (kc + 2) * 32); CP_COMMIT(); CP_WAIT(1); }
        else             { CP_WAIT(0); }
        __syncthreads();
        compute((const float2*)(smf + 10240), (const float2*)(smf + 15360));
        __syncthreads();
    }

    float* __restrict__ tdst = g_T + (size_t)c * NPAIR;
#pragma unroll
    for (int mt = 0; mt < 2; ++mt) {
        int r = i0 + m0 + mt * 16 + g;
#pragma unroll
        for (int nt = 0; nt < 8; ++nt) {
            int cl = j0 + n0 + nt * 8 + 2 * t;
            *(float2*)(tdst + (size_t)r * NROW + cl) =
                make_float2(acc[mt][nt][0], acc[mt][nt][1]);
            *(float2*)(tdst + (size_t)(r + 8) * NROW + cl) =
                make_float2(acc[mt][nt][2], acc[mt][nt][3]);
        }
    }
}

// ============================================================================
// final: out[pair][cz] = g * (LN_c(t) @ Wz + bz). 64-pair tiles, grid 4096.
// t gathered via cp.async; gate in natural layout (coalesced with out).
// smem = As(128x72) + Wc(64x136) + stats = 74240B -> 3 CTAs/SM.
// ============================================================================
__global__ __launch_bounds__(256, 3) void final_kernel(
    const float* __restrict__ lnw, const float* __restrict__ lnb,
    const float* __restrict__ bz, float* __restrict__ out)
{
    extern __shared__ float smf[];
    float* As = smf;                 // [128 c][72 pair] k-major
    float* Wc = As + 128 * 72;       // 64 x 136
    float* PS = Wc + 64 * 136;       // 256
    float* PQ = PS + 256;            // 256
    float* MS = PQ + 256;            // 64
    float* RS = MS + 64;             // 64
    const int tid = threadIdx.x;
    const int wid = tid >> 5, lane = tid & 31;
    const int g = lane >> 2, t = lane & 3;
    const int m0 = (wid & 3) * 16, n0 = (wid >> 2) * 32;
    const int p = tid & 63, ch = tid >> 6;
    const size_t pair0 = (size_t)blockIdx.x * 64;
    const u32 smb = smem_u32(smf);

    // ---- async gather of t: 2048 x 16B ----
#pragma unroll
    for (int it = 0; it < 8; ++it) {
        int lin = it * 256 + tid;        // 0..2047
        int c = lin >> 4, p4 = lin & 15;
        cpa16(smb + (u32)(c * 72 + p4 * 4) * 4u,
              g_T + (size_t)c * NPAIR + pair0 + p4 * 4);
    }
    CP_COMMIT();
    CP_WAIT(0);
    __syncthreads();

    // ---- stats from smem ----
    {
        float s = 0.f, qq = 0.f;
#pragma unroll 4
        for (int cc = 0; cc < 32; ++cc) {
            int c = ch * 32 + cc;
            float v = As[c * 72 + p];
            s += v; qq += v * v;
        }
        PS[tid] = s; PQ[tid] = qq;
    }
    __syncthreads();
    if (tid < 64) {
        float ss = PS[tid] + PS[tid + 64] + PS[tid + 128] + PS[tid + 192];
        float sq = PQ[tid] + PQ[tid + 64] + PQ[tid + 128] + PQ[tid + 192];
        float m = ss * (1.0f / 128.0f);
        MS[tid] = m;
        RS[tid] = rsqrtf(fmaxf(sq * (1.0f / 128.0f) - m * m, 0.f) + 1e-5f);
    }
    __syncthreads();

    // normalize in place
    {
        float mp = MS[p], rp = RS[p];
#pragma unroll 4
        for (int cc = 0; cc < 32; ++cc) {
            int c = ch * 32 + cc;
            float lw = __ldg(lnw + c), lb = __ldg(lnb + c);
            As[c * 72 + p] = tf32r((As[c * 72 + p] - mp) * rp * lw + lb);
        }
    }

    const float2* Wc2 = (const float2*)Wc;
    const int boff0 = (n0 + g) * 68 + t;
    const int r = m0 + g;

#pragma unroll 1
    for (int cb = 0; cb < 128; cb += 64) {
        __syncthreads();
        loadWc(Wc, 5, cb, tid);
        __syncthreads();

        float acc[4][4];
#pragma unroll
        for (int i = 0; i < 4; ++i)
#pragma unroll
            for (int q = 0; q < 4; ++q) acc[i][q] = 0.f;

#pragma unroll
        for (int ks = 0; ks < 16; ++ks) {
            const int k0 = ks * 8;
            const float* ap = As + (k0 + t) * 72 + m0 + g;
            u32 aa[4] = { __float_as_uint(ap[0]),      __float_as_uint(ap[8]),
                          __float_as_uint(ap[4 * 72]), __float_as_uint(ap[4 * 72 + 8]) };
#pragma unroll
            for (int nt = 0; nt < 4; ++nt) {
                float2 b = Wc2[boff0 + nt * 8 * 68 + ks * 4];
                u32 bb[2] = { __float_as_uint(b.x), __float_as_uint(b.y) };
                mma8(acc[nt], aa, bb);
            }
        }

#pragma unroll
        for (int nt = 0; nt < 4; ++nt) {
            int c = cb + n0 + nt * 8 + 2 * t;
            float2 bzv = *(const float2*)(bz + c);
            float2 gv0 = *(const float2*)(g_G + (pair0 + r) * (size_t)CZ + c);
            float2 gv1 = *(const float2*)(g_G + (pair0 + r + 8) * (size_t)CZ + c);
            *(float2*)(out + (pair0 + r) * (size_t)CZ + c) =
                make_float2(gv0.x * (acc[nt][0] + bzv.x), gv0.y * (acc[nt][1] + bzv.y));
            *(float2*)(out + (pair0 + r + 8) * (size_t)CZ + c) =
                make_float2(gv1.x * (acc[nt][2] + bzv.x), gv1.y * (acc[nt][3] + bzv.y));
        }
    }
}

// ============================================================================
// kernel_launch — sequential, single stream
// ============================================================================
extern "C" void kernel_launch(void* const* d_in, const int* in_sizes, int n_in,
                              void* d_out, int out_size)
{
    const float* z        = (const float*)d_in[0];
    const float* ln_in_w  = (const float*)d_in[1];
    const float* ln_in_b  = (const float*)d_in[2];
    const float* ln_out_w = (const float*)d_in[3];
    const float* ln_out_b = (const float*)d_in[4];
    const float* w_ap     = (const float*)d_in[5];
    const float* b_ap     = (const float*)d_in[6];
    const float* w_ag     = (const float*)d_in[7];
    const float* b_ag     = (const float*)d_in[8];
    const float* w_bp     = (const float*)d_in[9];
    const float* b_bp     = (const float*)d_in[10];
    const float* w_bg     = (const float*)d_in[11];
    const float* b_bg     = (const float*)d_in[12];
    const float* w_g      = (const float*)d_in[13];
    const float* b_g      = (const float*)d_in[14];
    const float* w_z      = (const float*)d_in[15];
    const float* b_z      = (const float*)d_in[16];
    float* out = (float*)d_out;

    const int PROJ_SMEM = (128 * 136 + 64 * 136) * 4;          // 104448
    const int TRI_SMEM  = 2 * 10240 * 4;                       // 81920
    const int FIN_SMEM  = (128 * 72 + 64 * 136 + 640) * 4;     // 74240

    cudaFuncSetAttribute(proj_all_kernel, cudaFuncAttributeMaxDynamicSharedMemorySize, PROJ_SMEM);
    cudaFuncSetAttribute(tri_kernel,      cudaFuncAttributeMaxDynamicSharedMemorySize, TRI_SMEM);
    cudaFuncSetAttribute(final_kernel,    cudaFuncAttributeMaxDynamicSharedMemorySize, FIN_SMEM);

    dim3 pgrid(64, 6);
    prep_w<<<pgrid, 256>>>(w_ap, w_ag, w_bp, w_bg, w_g, w_z);

    proj_all_kernel<<<NPAIR / 128, 256, PROJ_SMEM>>>(
        z, ln_in_w, ln_in_b, b_ap, b_ag, b_bp, b_bg, b_g);

    dim3 tgrid(4, 4, 128);
    tri_kernel<<<tgrid, 256, TRI_SMEM>>>();

    final_kernel<<<NPAIR / 64, 256, FIN_SMEM>>>(ln_out_w, ln_out_b, b_z, out);
}

// round 13
// speedup vs baseline: 1.1783x; 1.0614x over previous
#include <cuda_runtime.h>
#include <math.h>

#define NROW 512
#define CZ   128
#define NPAIR (NROW * NROW) /* 262144 */

typedef unsigned int u32;

// ---------------- device scratch ----------------
__device__ float g_A[(size_t)CZ * NPAIR];   // a, [c][i*512 + k] natural
__device__ float g_B[(size_t)CZ * NPAIR];   // b, [c][j*512 + k] natural
__device__ float g_G[(size_t)NPAIR * CZ];   // gate, [pair][cz]
__device__ float g_T[(size_t)CZ * NPAIR];   // t, [c][i*512+j]
__device__ float g_wt[6 * 128 * 128];       // weights transposed [n][k] natural
// img order: 0 w_ap, 1 w_ag, 2 w_bp, 3 w_bg, 4 w_g, 5 w_z

// ---------------- helpers ----------------
__device__ __forceinline__ float tf32r(float x) {
    float r;
    asm("cvt.rna.tf32.f32 %0, %1;" : "=f"(r) : "f"(x));
    return r;
}
__device__ __forceinline__ float wsum(float v) {
#pragma unroll
    for (int o = 16; o; o >>= 1) v += __shfl_xor_sync(0xffffffffu, v, o);
    return v;
}
__device__ __forceinline__ float sigm(float x) {
    return 1.0f / (1.0f + __expf(-x));
}
__device__ __forceinline__ void mma8(float* d, const u32* a, const u32* b) {
    asm volatile(
        "mma.sync.aligned.m16n8k8.row.col.f32.tf32.tf32.f32 "
        "{%0,%1,%2,%3}, {%4,%5,%6,%7}, {%8,%9}, {%0,%1,%2,%3};"
        : "+f"(d[0]), "+f"(d[1]), "+f"(d[2]), "+f"(d[3])
        : "r"(a[0]), "r"(a[1]), "r"(a[2]), "r"(a[3]), "r"(b[0]), "r"(b[1]));
}
__device__ __forceinline__ u32 smem_u32(const void* p) {
    u32 a;
    asm("{ .reg .u64 t; cvta.to.shared.u64 t, %1; cvt.u32.u64 %0, t; }" : "=r"(a) : "l"(p));
    return a;
}
__device__ __forceinline__ void cpa16(u32 dst, const void* src) {
    asm volatile("cp.async.cg.shared.global [%0], [%1], 16;" :: "r"(dst), "l"(src));
}
#define CP_COMMIT() asm volatile("cp.async.commit_group;" ::: "memory")
#define CP_WAIT(n)  asm volatile("cp.async.wait_group %0;" :: "n"(n) : "memory")

// ldmatrix x4: one 16x8-f32 A fragment (a0..a3) OR two n8k8 B fragments.
#define LDSM4(R, ADDR) \
    asm volatile("ldmatrix.sync.aligned.m8n8.x4.shared.b16 {%0,%1,%2,%3}, [%4];" \
        : "=r"((R)[0]), "=r"((R)[1]), "=r"((R)[2]), "=r"((R)[3]) : "r"(ADDR))

// ============================================================================
// prep: transpose + tf32-round weights into natural [n][k] layout
// ============================================================================
__global__ void prep_w(const float* __restrict__ wap, const float* __restrict__ wag,
                       const float* __restrict__ wbp, const float* __restrict__ wbg,
                       const float* __restrict__ wg,  const float* __restrict__ wz) {
    int img = blockIdx.y;
    int lin = blockIdx.x * 256 + threadIdx.x;
    int n = lin >> 7, k = lin & 127;
    const float* s;
    switch (img) {
        case 0: s = wap; break; case 1: s = wag; break;
        case 2: s = wbp; break; case 3: s = wbg; break;
        case 4: s = wg;  break; default: s = wz; break;
    }
    g_wt[img * 16384 + lin] = tf32r(s[k * 128 + n]);
}

// ============================================================================
// load a 64-row weight chunk into Wc (row stride 132 floats = 33 float4)
// ============================================================================
__device__ __forceinline__ void loadWc(float* __restrict__ Wc, int img, int nb, int tid) {
    const float4* src = (const float4*)(g_wt + img * 16384);
#pragma unroll
    for (int it = 0; it < 8; ++it) {
        int lin = it * 256 + tid;          // 0..2047
        int row = lin >> 5, q = lin & 31;
        ((float4*)Wc)[row * 33 + q] = src[(nb + row) * 32 + q];
    }
}

// LDSM lane roles (A fragment: groups = rows0-7 klo, rows8-15 klo, rows0-7 khi, rows8-15 khi)
#define ROWA(lane) ((lane) & 15)
#define KHA(lane)  ((lane) >> 4)
// (B fragments: groups = n0-7 klo, n0-7 khi, n8-15 klo, n8-15 khi)
#define ROWB(lane) (((lane) & 7) | (((lane) >> 4) << 3))
#define KHB(lane)  (((lane) >> 3) & 1)

// ============================================================================
// GEMM: warp tile m32 x n32, K=128, LDSM fragments.
// As (128 rows x 132 stride), Wc (64 rows x 132 stride). acc[2][4][4].
// ============================================================================
__device__ __forceinline__ void gemm32x32(u32 asb, u32 wcb, float acc[2][4][4]) {
#pragma unroll
    for (int m = 0; m < 2; ++m)
#pragma unroll
        for (int i = 0; i < 4; ++i)
#pragma unroll
            for (int q = 0; q < 4; ++q) acc[m][i][q] = 0.f;
#pragma unroll
    for (int ks = 0; ks < 16; ++ks) {
        u32 a0[4], a1[4], b0[4], b1[4];
        LDSM4(a0, asb + ks * 32);
        LDSM4(a1, asb + 16 * 132 * 4 + ks * 32);
        LDSM4(b0, wcb + ks * 32);
        LDSM4(b1, wcb + 16 * 132 * 4 + ks * 32);
        mma8(acc[0][0], a0, b0);     mma8(acc[0][1], a0, b0 + 2);
        mma8(acc[0][2], a0, b1);     mma8(acc[0][3], a0, b1 + 2);
        mma8(acc[1][0], a1, b0);     mma8(acc[1][1], a1, b0 + 2);
        mma8(acc[1][2], a1, b1);     mma8(acc[1][3], a1, b1 + 2);
    }
}

// ============================================================================
// proj_all: FUSED. 128-pair tiles, warp tile m32n32, LN once, then
// ap||ag -> g_A, bp||bg -> g_B, g -> g_G. All natural layouts.
// smem = As(128x132)+Wc(64x132) = 101376B -> 2 CTAs/SM.
// ============================================================================
__global__ __launch_bounds__(256, 2) void proj_all_kernel(
    const float* __restrict__ z,
    const float* __restrict__ lnw, const float* __restrict__ lnb,
    const float* __restrict__ b_ap, const float* __restrict__ b_ag,
    const float* __restrict__ b_bp, const float* __restrict__ b_bg,
    const float* __restrict__ b_g)
{
    extern __shared__ float smf[];
    float* As = smf;                 // 128 x 132
    float* Wc = smf + 128 * 132;     // 64 x 132
    const int tid = threadIdx.x;
    const int wid = tid >> 5, lane = tid & 31;
    const int g = lane >> 2, t = lane & 3;
    const int m0 = (wid & 3) * 32, n0 = (wid >> 2) * 32;
    const size_t pair0 = (size_t)blockIdx.x * 128;

    // ---- LN -> As (natural k order) ----
    {
        float4 lw = ((const float4*)lnw)[lane];
        float4 lb = ((const float4*)lnb)[lane];
#pragma unroll 2
        for (int r = 0; r < 16; ++r) {
            int row = wid * 16 + r;
            float4 x = ((const float4*)(z + (pair0 + row) * (size_t)CZ))[lane];
            float m = wsum(x.x + x.y + x.z + x.w) * (1.0f / 128.0f);
            float dx = x.x - m, dy = x.y - m, dz = x.z - m, dw = x.w - m;
            float var = wsum(dx * dx + dy * dy + dz * dz + dw * dw) * (1.0f / 128.0f);
            float rs = rsqrtf(var + 1e-5f);
            float4 o;
            o.x = tf32r(dx * rs * lw.x + lb.x);
            o.y = tf32r(dy * rs * lw.y + lb.y);
            o.z = tf32r(dz * rs * lw.z + lb.z);
            o.w = tf32r(dw * rs * lw.w + lb.w);
            *(float4*)(As + row * 132 + lane * 4) = o;
        }
    }

    const u32 asbase = smem_u32(As);
    const u32 wcbase = smem_u32(Wc);
    const u32 asb = asbase + (u32)((m0 + ROWA(lane)) * 132 + KHA(lane) * 4) * 4u;
    const u32 wcb = wcbase + (u32)((n0 + ROWB(lane)) * 132 + KHB(lane) * 4) * 4u;
    const int r0 = m0 + g, r1 = m0 + 16 + g;

    float accg[2][4][4], accp[2][4][4];

    // ---- a then b ----
#pragma unroll 1
    for (int sel = 0; sel < 2; ++sel) {
        const int imgP = sel * 2, imgG = sel * 2 + 1;
        const float* bp = sel ? b_bp : b_ap;
        const float* bg = sel ? b_bg : b_ag;
        float* __restrict__ dst = sel ? g_B : g_A;
#pragma unroll 1
        for (int cb = 0; cb < 128; cb += 64) {
            __syncthreads();
            loadWc(Wc, imgG, cb, tid);
            __syncthreads();
            gemm32x32(asb, wcb, accg);
            __syncthreads();
            loadWc(Wc, imgP, cb, tid);
            __syncthreads();
            gemm32x32(asb, wcb, accp);
#pragma unroll
            for (int mt = 0; mt < 2; ++mt) {
                const int r = mt ? r1 : r0;
#pragma unroll
                for (int nt = 0; nt < 4; ++nt) {
                    int c = cb + n0 + nt * 8 + 2 * t;
                    float2 bpv = *(const float2*)(bp + c);
                    float2 bgv = *(const float2*)(bg + c);
                    float* d0 = dst + (size_t)c * NPAIR + pair0;
                    float* d1 = dst + (size_t)(c + 1) * NPAIR + pair0;
                    const float* P = accp[mt][nt];
                    const float* G = accg[mt][nt];
                    d0[r]     = tf32r(sigm(G[0] + bgv.x) * (P[0] + bpv.x));
                    d1[r]     = tf32r(sigm(G[1] + bgv.y) * (P[1] + bpv.y));
                    d0[r + 8] = tf32r(sigm(G[2] + bgv.x) * (P[2] + bpv.x));
                    d1[r + 8] = tf32r(sigm(G[3] + bgv.y) * (P[3] + bpv.y));
                }
            }
        }
    }

    // ---- gate g (natural rows, float2 stores) ----
#pragma unroll 1
    for (int cb = 0; cb < 128; cb += 64) {
        __syncthreads();
        loadWc(Wc, 4, cb, tid);
        __syncthreads();
        gemm32x32(asb, wcb, accg);
#pragma unroll
        for (int mt = 0; mt < 2; ++mt) {
            const int r = mt ? r1 : r0;
#pragma unroll
            for (int nt = 0; nt < 4; ++nt) {
                int c = cb + n0 + nt * 8 + 2 * t;
                float2 bgv = *(const float2*)(b_g + c);
                const float* G = accg[mt][nt];
                *(float2*)(g_G + (pair0 + r) * (size_t)CZ + c) =
                    make_float2(sigm(G[0] + bgv.x), sigm(G[1] + bgv.y));
                *(float2*)(g_G + (pair0 + r + 8) * (size_t)CZ + c) =
                    make_float2(sigm(G[2] + bgv.x), sigm(G[3] + bgv.y));
            }
        }
    }
}

// ============================================================================
// tri: t[c][i][j] = sum_k a[c][i][k]*b[c][j][k]; 128x128 tile, K chunks of 32,
// cp.async double-buffered, LDSM fragments. Buffers: A/B 128 rows x 36 stride.
// smem = 4 x 18432 = 73728B -> 2 CTAs/SM.
// ============================================================================
__global__ __launch_bounds__(256, 2) void tri_kernel()
{
    extern __shared__ float smf[];   // [A0 4608f | B0 4608f | A1 | B1]
    const int tid = threadIdx.x;
    const int wid = tid >> 5, lane = tid & 31;
    const int g = lane >> 2, t = lane & 3;
    const int m0 = (wid & 3) * 32, n0 = (wid >> 2) * 64;
    const int c  = blockIdx.z;
    const int i0 = blockIdx.y * 128;
    const int j0 = blockIdx.x * 128;
    const float* __restrict__ asrc = g_A + (size_t)c * NPAIR + (size_t)i0 * NROW;
    const float* __restrict__ bsrc = g_B + (size_t)c * NPAIR + (size_t)j0 * NROW;
    const u32 smb = smem_u32(smf);

    // hoisted per-thread copy offsets
    int offg[4];      // gmem float offset (row*NROW + j*4)
    u32 offs[4];      // smem byte offset within a buffer
#pragma unroll
    for (int it = 0; it < 4; ++it) {
        int lin = it * 256 + tid, row = lin >> 3, j = lin & 7;
        offg[it] = row * NROW + j * 4;
        offs[it] = (u32)(row * 36 + j * 4) * 4u;
    }
    const u32 bufA0 = smb;
    const u32 bufB0 = smb + 4608u * 4u;
    const u32 bufA1 = smb + 9216u * 4u;
    const u32 bufB1 = smb + 13824u * 4u;

    float acc[2][8][4];
#pragma unroll
    for (int i = 0; i < 2; ++i)
#pragma unroll
        for (int j = 0; j < 8; ++j)
#pragma unroll
            for (int q = 0; q < 4; ++q) acc[i][j][q] = 0.f;

    // LDSM fragment base offsets (bytes) within a buffer
    const u32 aofs = (u32)((m0 + ROWA(lane)) * 36 + KHA(lane) * 4) * 4u;
    const u32 bofs = (u32)((n0 + ROWB(lane)) * 36 + KHB(lane) * 4) * 4u;

    auto issue2 = [&](u32 baseA, u32 baseB, int k0) {
#pragma unroll
        for (int it = 0; it < 4; ++it) {
            cpa16(baseA + offs[it], asrc + offg[it] + k0);
            cpa16(baseB + offs[it], bsrc + offg[it] + k0);
        }
    };

    auto compute = [&](u32 baseA, u32 baseB) {
#pragma unroll
        for (int ks = 0; ks < 4; ++ks) {
            u32 a0[4], a1[4];
            LDSM4(a0, baseA + aofs + ks * 32);
            LDSM4(a1, baseA + aofs + 16 * 36 * 4 + ks * 32);
#pragma unroll
            for (int s = 0; s < 4; ++s) {
                u32 b[4];
                LDSM4(b, baseB + bofs + (u32)(s * 16 * 36 * 4) + ks * 32);
                mma8(acc[0][s * 2],     a0, b);
                mma8(acc[0][s * 2 + 1], a0, b + 2);
                mma8(acc[1][s * 2],     a1, b);
                mma8(acc[1][s * 2 + 1], a1, b + 2);
            }
        }
    };

    issue2(bufA0, bufB0, 0); CP_COMMIT();

#pragma unroll 1
    for (int kc2 = 0; kc2 < 8; ++kc2) {
        const int kc = kc2 * 2;
        issue2(bufA1, bufB1, (kc + 1) * 32); CP_COMMIT(); CP_WAIT(1);
        __syncthreads();
        compute(bufA0, bufB0);
        __syncthreads();
        if (kc + 2 < 16) { issue2(bufA0, bufB0, (kc + 2) * 32); CP_COMMIT(); CP_WAIT(1); }
        else             { CP_WAIT(0); }
        __syncthreads();
        compute(bufA1, bufB1);
        __syncthreads();
    }

    float* __restrict__ tdst = g_T + (size_t)c * NPAIR;
#pragma unroll
    for (int mt = 0; mt < 2; ++mt) {
        int r = i0 + m0 + mt * 16 + g;
#pragma unroll
        for (int nt = 0; nt < 8; ++nt) {
            int cl = j0 + n0 + nt * 8 + 2 * t;
            *(float2*)(tdst + (size_t)r * NROW + cl) =
                make_float2(acc[mt][nt][0], acc[mt][nt][1]);
            *(float2*)(tdst + (size_t)(r + 8) * NROW + cl) =
                make_float2(acc[mt][nt][2], acc[mt][nt][3]);
        }
    }
}

// ============================================================================
// final: out[pair][cz] = g * (LN_c(t) @ Wz + bz). 64-pair tiles, grid 4096.
// t via cp.async; B fragments via LDSM (Wc 64x132).
// smem = As(128x72) + Wc(64x132) + stats = 73216B -> 3 CTAs/SM.
// ============================================================================
__global__ __launch_bounds__(256, 3) void final_kernel(
    const float* __restrict__ lnw, const float* __restrict__ lnb,
    const float* __restrict__ bz, float* __restrict__ out)
{
    extern __shared__ float smf[];
    float* As = smf;                 // [128 c][72 pair] k-major
    float* Wc = As + 128 * 72;       // 64 x 132
    float* PS = Wc + 64 * 132;       // 256
    float* PQ = PS + 256;            // 256
    float* MS = PQ + 256;            // 64
    float* RS = MS + 64;             // 64
    const int tid = threadIdx.x;
    const int wid = tid >> 5, lane = tid & 31;
    const int g = lane >> 2, t = lane & 3;
    const int m0 = (wid & 3) * 16, n0 = (wid >> 2) * 32;
    const int p = tid & 63, ch = tid >> 6;
    const size_t pair0 = (size_t)blockIdx.x * 64;
    const u32 smb = smem_u32(smf);

    // ---- async gather of t: 2048 x 16B ----
#pragma unroll
    for (int it = 0; it < 8; ++it) {
        int lin = it * 256 + tid;        // 0..2047
        int c = lin >> 4, p4 = lin & 15;
        cpa16(smb + (u32)(c * 72 + p4 * 4) * 4u,
              g_T + (size_t)c * NPAIR + pair0 + p4 * 4);
    }
    CP_COMMIT();
    CP_WAIT(0);
    __syncthreads();

    // ---- stats from smem ----
    {
        float s = 0.f, qq = 0.f;
#pragma unroll 4
        for (int cc = 0; cc < 32; ++cc) {
            int c = ch * 32 + cc;
            float v = As[c * 72 + p];
            s += v; qq += v * v;
        }
        PS[tid] = s; PQ[tid] = qq;
    }
    __syncthreads();
    if (tid < 64) {
        float ss = PS[tid] + PS[tid + 64] + PS[tid + 128] + PS[tid + 192];
        float sq = PQ[tid] + PQ[tid + 64] + PQ[tid + 128] + PQ[tid + 192];
        float m = ss * (1.0f / 128.0f);
        MS[tid] = m;
        RS[tid] = rsqrtf(fmaxf(sq * (1.0f / 128.0f) - m * m, 0.f) + 1e-5f);
    }
    __syncthreads();

    // normalize in place
    {
        float mp = MS[p], rp = RS[p];
#pragma unroll 4
        for (int cc = 0; cc < 32; ++cc) {
            int c = ch * 32 + cc;
            float lw = __ldg(lnw + c), lb = __ldg(lnb + c);
            As[c * 72 + p] = tf32r((As[c * 72 + p] - mp) * rp * lw + lb);
        }
    }

    const u32 wcb = smem_u32(Wc) +
        (u32)((n0 + ROWB(lane)) * 132 + KHB(lane) * 4) * 4u;
    const int r = m0 + g;

#pragma unroll 1
    for (int cb = 0; cb < 128; cb += 64) {
        __syncthreads();
        loadWc(Wc, 5, cb, tid);
        __syncthreads();

        float acc[4][4];
#pragma unroll
        for (int i = 0; i < 4; ++i)
#pragma unroll
            for (int q = 0; q < 4; ++q) acc[i][q] = 0.f;

#pragma unroll
        for (int ks = 0; ks < 16; ++ks) {
            const int k0 = ks * 8;
            const float* ap = As + (k0 + t) * 72 + m0 + g;
            u32 aa[4] = { __float_as_uint(ap[0]),      __float_as_uint(ap[8]),
                          __float_as_uint(ap[4 * 72]), __float_as_uint(ap[4 * 72 + 8]) };
            u32 b[4];
            LDSM4(b, wcb + ks * 32);
            mma8(acc[0], aa, b);
            mma8(acc[1], aa, b + 2);
            u32 b2[4];
            LDSM4(b2, wcb + 16 * 132 * 4 + ks * 32);
            mma8(acc[2], aa, b2);
            mma8(acc[3], aa, b2 + 2);
        }

#pragma unroll
        for (int nt = 0; nt < 4; ++nt) {
            int c = cb + n0 + nt * 8 + 2 * t;
            float2 bzv = *(const float2*)(bz + c);
            float2 gv0 = *(const float2*)(g_G + (pair0 + r) * (size_t)CZ + c);
            float2 gv1 = *(const float2*)(g_G + (pair0 + r + 8) * (size_t)CZ + c);
            *(float2*)(out + (pair0 + r) * (size_t)CZ + c) =
                make_float2(gv0.x * (acc[nt][0] + bzv.x), gv0.y * (acc[nt][1] + bzv.y));
            *(float2*)(out + (pair0 + r + 8) * (size_t)CZ + c) =
                make_float2(gv1.x * (acc[nt][2] + bzv.x), gv1.y * (acc[nt][3] + bzv.y));
        }
    }
}

// ============================================================================
// kernel_launch — sequential, single stream
// ============================================================================
extern "C" void kernel_launch(void* const* d_in, const int* in_sizes, int n_in,
                              void* d_out, int out_size)
{
    const float* z        = (const float*)d_in[0];
    const float* ln_in_w  = (const float*)d_in[1];
    const float* ln_in_b  = (const float*)d_in[2];
    const float* ln_out_w = (const float*)d_in[3];
    const float* ln_out_b = (const float*)d_in[4];
    const float* w_ap     = (const float*)d_in[5];
    const float* b_ap     = (const float*)d_in[6];
    const float* w_ag     = (const float*)d_in[7];
    const float* b_ag     = (const float*)d_in[8];
    const float* w_bp     = (const float*)d_in[9];
    const float* b_bp     = (const float*)d_in[10];
    const float* w_bg     = (const float*)d_in[11];
    const float* b_bg     = (const float*)d_in[12];
    const float* w_g      = (const float*)d_in[13];
    const float* b_g      = (const float*)d_in[14];
    const float* w_z      = (const float*)d_in[15];
    const float* b_z      = (const float*)d_in[16];
    float* out = (float*)d_out;

    const int PROJ_SMEM = (128 * 132 + 64 * 132) * 4;          // 101376
    const int TRI_SMEM  = 4 * 4608 * 4;                        // 73728
    const int FIN_SMEM  = (128 * 72 + 64 * 132 + 640) * 4;     // 73216

    cudaFuncSetAttribute(proj_all_kernel, cudaFuncAttributeMaxDynamicSharedMemorySize, PROJ_SMEM);
    cudaFuncSetAttribute(tri_kernel,      cudaFuncAttributeMaxDynamicSharedMemorySize, TRI_SMEM);
    cudaFuncSetAttribute(final_kernel,    cudaFuncAttributeMaxDynamicSharedMemorySize, FIN_SMEM);

    dim3 pgrid(64, 6);
    prep_w<<<pgrid, 256>>>(w_ap, w_ag, w_bp, w_bg, w_g, w_z);

    proj_all_kernel<<<NPAIR / 128, 256, PROJ_SMEM>>>(
        z, ln_in_w, ln_in_b, b_ap, b_ag, b_bp, b_bg, b_g);

    dim3 tgrid(4, 4, 128);
    tri_kernel<<<tgrid, 256, TRI_SMEM>>>();

    final_kernel<<<NPAIR / 64, 256, FIN_SMEM>>>(ln_out_w, ln_out_b, b_z, out);
}